// round 14
// baseline (speedup 1.0000x reference)
#include <cuda_runtime.h>
#include <cuda_fp16.h>
#include <math.h>
#include <stdint.h>

// Problem constants
#define BSZ 2
#define T   2048
#define C   2048
#define NH  16
#define DH  128
#define MROWS (BSZ * T)      // 4096
#define KDIM  C              // 2048
#define NDIM  C              // 2048

// Scratch (fp16 activations/weights; fp32 only at the final output)
__device__ __half  g_a[MROWS * KDIM];            // fp16 src
__device__ uint32_t g_w0[(KDIM / 2) * NDIM];     // Wq packed half2 (k-interleaved)
__device__ uint32_t g_w1[(KDIM / 2) * NDIM];
__device__ uint32_t g_w2[(KDIM / 2) * NDIM];
__device__ uint32_t g_w3[(KDIM / 2) * NDIM];
__device__ __half  g_q[BSZ * NH * T * DH];       // heads layout [b,h,t,d]
__device__ __half  g_k[BSZ * NH * T * DH];
__device__ __half  g_v[BSZ * NH * T * DH];
__device__ __half  g_o[BSZ * NH * T * DH];

// ---------------------------------------------------------------------------
// PTX helpers
// ---------------------------------------------------------------------------
__device__ __forceinline__ uint32_t smem_u32(const void* p) {
    uint32_t a;
    asm("{ .reg .u64 t; cvta.to.shared.u64 t, %1; cvt.u32.u64 %0, t; }"
        : "=r"(a) : "l"(p));
    return a;
}

__device__ __forceinline__ float fast_exp2(float x) {
    float y;
    asm("ex2.approx.f32 %0, %1;" : "=f"(y) : "f"(x));
    return y;
}

__device__ __forceinline__ uint32_t pack2(float lo, float hi) {
    __half2 h = __floats2half2_rn(lo, hi);
    return *(uint32_t*)&h;
}

__device__ __forceinline__ void cp16(uint32_t dst, const void* src) {
    asm volatile("cp.async.cg.shared.global [%0], [%1], 16;"
                 :: "r"(dst), "l"(src));
}
#define CP_COMMIT() asm volatile("cp.async.commit_group;" ::: "memory")
template <int N>
__device__ __forceinline__ void cp_wait() {
    asm volatile("cp.async.wait_group %0;" :: "n"(N) : "memory");
}

__device__ __forceinline__ void ldsm4(uint32_t& r0, uint32_t& r1,
                                      uint32_t& r2, uint32_t& r3, uint32_t a) {
    asm volatile("ldmatrix.sync.aligned.m8n8.x4.shared.b16 {%0,%1,%2,%3}, [%4];"
                 : "=r"(r0), "=r"(r1), "=r"(r2), "=r"(r3) : "r"(a));
}
__device__ __forceinline__ void ldsm4t(uint32_t& r0, uint32_t& r1,
                                       uint32_t& r2, uint32_t& r3, uint32_t a) {
    asm volatile("ldmatrix.sync.aligned.m8n8.x4.trans.shared.b16 {%0,%1,%2,%3}, [%4];"
                 : "=r"(r0), "=r"(r1), "=r"(r2), "=r"(r3) : "r"(a));
}

__device__ __forceinline__ void mma_f16_16n8k16(
    float& d0, float& d1, float& d2, float& d3,
    uint32_t a0, uint32_t a1, uint32_t a2, uint32_t a3,
    uint32_t b0, uint32_t b1)
{
    asm volatile(
        "mma.sync.aligned.m16n8k16.row.col.f32.f16.f16.f32 "
        "{%0,%1,%2,%3}, {%4,%5,%6,%7}, {%8,%9}, {%0,%1,%2,%3};\n"
        : "+f"(d0), "+f"(d1), "+f"(d2), "+f"(d3)
        : "r"(a0), "r"(a1), "r"(a2), "r"(a3), "r"(b0), "r"(b1));
}

// ---------------------------------------------------------------------------
// Pre-pass: y==0 converts src fp32->fp16; y==1..4 pack weights into
// k-interleaved half2: wp[k2*N + n] = half2(W[2k2][n], W[2k2+1][n]).
// ---------------------------------------------------------------------------
struct ConvArgs {
    const float* w[4];
    uint32_t*    wp[4];
    const float4* src;
    uint2*        a_out;
    int           src_n;
};

__global__ void convert_kernel(ConvArgs ca) {
    const int y = blockIdx.y;
    if (y == 0) {
        int i = blockIdx.x * blockDim.x + threadIdx.x;
        const int stride = gridDim.x * blockDim.x;
        for (; i < ca.src_n; i += stride) {
            float4 v = ca.src[i];
            uint2 o;
            o.x = pack2(v.x, v.y);
            o.y = pack2(v.z, v.w);
            ca.a_out[i] = o;
        }
    } else {
        const float* W  = ca.w[y - 1];
        uint32_t*    wp = ca.wp[y - 1];
        const int total = (KDIM / 2) * (NDIM / 4);
        int i = blockIdx.x * blockDim.x + threadIdx.x;
        const int stride = gridDim.x * blockDim.x;
        for (; i < total; i += stride) {
            const int k2 = i >> 9;
            const int nc = (i & 511) * 4;
            const float4 r0 = *(const float4*)&W[(size_t)(2 * k2)     * NDIM + nc];
            const float4 r1 = *(const float4*)&W[(size_t)(2 * k2 + 1) * NDIM + nc];
            uint4 o;
            o.x = pack2(r0.x, r1.x);
            o.y = pack2(r0.y, r1.y);
            o.z = pack2(r0.z, r1.z);
            o.w = pack2(r0.w, r1.w);
            *(uint4*)&wp[(size_t)k2 * NDIM + nc] = o;
        }
    }
}

// ---------------------------------------------------------------------------
// fp16 HMMA GEMM (R11 configuration): out = A @ W + bias
// Block tile 128x128, K-slab 64 (4 m16n8k16 steps), 3-stage cp.async,
// 256 threads, 8 warps (2x4), warp tile 64x32. A-frags via ldmatrix.x4;
// B-frags (scalar LDS) double-buffered across k16-steps.
// ---------------------------------------------------------------------------
#define BK 64
#define NKS (KDIM / BK)          // 32
#define STAGES 3
#define AS2 36
#define BS2 136
#define A_ST_U32 (128 * AS2)     // 4608
#define B_ST_U32 (32 * BS2)      // 4352
#define ST_U32 (A_ST_U32 + B_ST_U32)   // 8960
#define GEMM_SMEM (STAGES * ST_U32 * 4)  // 107520 bytes

template <bool GATHER_A, bool OUT_F32>
__device__ void gemm_body(
    const __half* __restrict__ A, const uint32_t* __restrict__ Wp,
    const float* __restrict__ bias, void* __restrict__ out_v,
    int m_base, int n_base)
{
    extern __shared__ uint32_t smu[];
    const uint32_t sb = smem_u32(smu);
    const int tid  = threadIdx.x;
    const int lane = tid & 31;
    const int w    = tid >> 5;
    const int wm   = (w >> 2) * 64;
    const int wn   = (w & 3) * 32;

    const int lm_row  = lane & 15;
    const int lm_koff = (lane & 16) >> 2;

    uint32_t a_off[4], b_off[4];
    const __half* a_fix[4];
    const uint32_t* b_fix[4];
#pragma unroll
    for (int i = 0; i < 4; i++) {
        const int g  = tid + i * 256;
        const int ar = g >> 3;
        const int ac = g & 7;
        a_off[i] = (uint32_t)(ar * AS2 + ac * 4) * 4;
        if (GATHER_A) {
            const int m = m_base + ar;
            a_fix[i] = A + (size_t)(m >> 11) * (NH * T * DH)
                         + (size_t)(m & 2047) * DH + ac * 8;
        } else {
            a_fix[i] = A + (size_t)(m_base + ar) * KDIM + ac * 8;
        }
        const int br = g >> 5;
        const int bc = g & 31;
        b_off[i] = (uint32_t)(A_ST_U32 + br * BS2 + bc * 4) * 4;
        b_fix[i] = Wp + (size_t)br * NDIM + n_base + bc * 4;
    }

    auto load_slab = [&](int ks) {
        const int s = ks % STAGES;
        const uint32_t stage = sb + (uint32_t)(s * ST_U32) * 4;
        const int k0 = ks * BK;
#pragma unroll
        for (int i = 0; i < 4; i++) {
            const __half* asrc;
            if (GATHER_A)
                asrc = a_fix[i] + (size_t)(k0 >> 7) * (T * DH) + (k0 & 127);
            else
                asrc = a_fix[i] + k0;
            cp16(stage + a_off[i], asrc);
            cp16(stage + b_off[i], b_fix[i] + (size_t)(k0 / 2) * NDIM);
        }
        CP_COMMIT();
    };

    float acc[4][4][4];
#pragma unroll
    for (int mf = 0; mf < 4; mf++)
#pragma unroll
        for (int nf = 0; nf < 4; nf++)
#pragma unroll
            for (int r = 0; r < 4; r++) acc[mf][nf][r] = 0.0f;

    load_slab(0);
    load_slab(1);

    const int qr = lane >> 2;
    const int qc = lane & 3;

    for (int ks = 0; ks < NKS; ks++) {
        if (ks >= NKS - 1) cp_wait<0>(); else cp_wait<1>();
        __syncthreads();
        if (ks + 2 < NKS) load_slab(ks + 2);

        const uint32_t st_off = (uint32_t)((ks % STAGES) * ST_U32);
        const uint32_t* Bs = smu + st_off + A_ST_U32;
        const uint32_t a_stage = sb + st_off * 4;

        uint32_t bfr[2][4][2];
#pragma unroll
        for (int nf = 0; nf < 4; nf++) {
            const int cn = wn + nf * 8 + qr;
            bfr[0][nf][0] = Bs[qc       * BS2 + cn];
            bfr[0][nf][1] = Bs[(qc + 4) * BS2 + cn];
        }

#pragma unroll
        for (int s2 = 0; s2 < 4; s2++) {
            const int cur = s2 & 1;
            if (s2 < 3) {
                const int pb = (s2 + 1) * 8;
#pragma unroll
                for (int nf = 0; nf < 4; nf++) {
                    const int cn = wn + nf * 8 + qr;
                    bfr[cur ^ 1][nf][0] = Bs[(pb + qc)     * BS2 + cn];
                    bfr[cur ^ 1][nf][1] = Bs[(pb + qc + 4) * BS2 + cn];
                }
            }
            const int pb = s2 * 8;
#pragma unroll
            for (int mf = 0; mf < 4; mf++) {
                uint32_t a0, a1, a2, a3;
                ldsm4(a0, a1, a2, a3,
                      a_stage + (uint32_t)((wm + mf * 16 + lm_row) * AS2
                                           + pb + lm_koff) * 4);
#pragma unroll
                for (int nf = 0; nf < 4; nf++)
                    mma_f16_16n8k16(acc[mf][nf][0], acc[mf][nf][1],
                                    acc[mf][nf][2], acc[mf][nf][3],
                                    a0, a1, a2, a3,
                                    bfr[cur][nf][0], bfr[cur][nf][1]);
            }
        }
    }

    // ---- epilogue ----
#pragma unroll
    for (int mf = 0; mf < 4; mf++) {
        const int row0 = m_base + wm + mf * 16 + qr;
#pragma unroll
        for (int nf = 0; nf < 4; nf++) {
            const int col = n_base + wn + nf * 8 + 2 * qc;
            const float bx = bias[col];
            const float by = bias[col + 1];
#pragma unroll
            for (int half_i = 0; half_i < 2; half_i++) {
                const int row = row0 + half_i * 8;
                const float vx = acc[mf][nf][half_i * 2 + 0] + bx;
                const float vy = acc[mf][nf][half_i * 2 + 1] + by;
                if (OUT_F32) {
                    float2 v; v.x = vx; v.y = vy;
                    *(float2*)&((float*)out_v)[(size_t)row * NDIM + col] = v;
                } else {
                    const int b = row >> 11, t = row & 2047;
                    const int h = col >> 7,  d = col & 127;
                    __half* ho = (__half*)out_v;
                    const size_t idx = (((size_t)b * NH + h) * T + t) * DH + d;
                    *(uint32_t*)&ho[idx] = pack2(vx, vy);
                }
            }
        }
    }
}

__global__ __launch_bounds__(256, 2) void qkv_gemm_kernel(
    const __half* __restrict__ A,
    const uint32_t* __restrict__ w0, const uint32_t* __restrict__ w1,
    const uint32_t* __restrict__ w2,
    const float* __restrict__ b0, const float* __restrict__ b1,
    const float* __restrict__ b2,
    __half* __restrict__ o0, __half* __restrict__ o1, __half* __restrict__ o2)
{
    const int z = blockIdx.z;
    const uint32_t* W  = (z == 0) ? w0 : (z == 1) ? w1 : w2;
    const float* bias  = (z == 0) ? b0 : (z == 1) ? b1 : b2;
    __half*      out   = (z == 0) ? o0 : (z == 1) ? o1 : o2;
    gemm_body<false, false>(A, W, bias, out,
                            blockIdx.y * 128, blockIdx.x * 128);
}

__global__ __launch_bounds__(256, 2) void o_gemm_kernel(
    const __half* __restrict__ A, const uint32_t* __restrict__ W,
    const float* __restrict__ bias, float* __restrict__ out)
{
    gemm_body<true, true>(A, W, bias, out,
                          blockIdx.y * 128, blockIdx.x * 128);
}

// ---------------------------------------------------------------------------
// fp16 flash attention (causal), SOFTWARE-PIPELINED across kv tiles:
// each barrier-to-barrier region contains S(kt+1) + PV(kt) (128 MMAs)
// against ONE softmax region. 3 KV buffers, BQ=128, BKV=64, 256 threads.
// smem (u32): KV[3][64][68]x2, P[128][36]  = 122880 bytes
// ---------------------------------------------------------------------------
#define FQ 128
#define FKV 64
#define KS2 68
#define VS2 68
#define PS2 36
#define NBUF 3
#define K_U32 (FKV * KS2)                // 4352
#define V_U32 (FKV * VS2)                // 4352
#define STG_U32 (K_U32 + V_U32)          // 8704
#define P_OFF_U32 (NBUF * STG_U32)       // 26112
#define FLASH_SMEM ((P_OFF_U32 + FQ * PS2) * 4)   // 122880 bytes

__global__ __launch_bounds__(256) void flash4_kernel(
    const __half* __restrict__ gq, const __half* __restrict__ gk,
    const __half* __restrict__ gv, __half* __restrict__ gout)
{
    extern __shared__ uint32_t smu[];
    const uint32_t sb = smem_u32(smu);
    const int tid  = threadIdx.x;
    const int lane = tid & 31;
    const int w    = tid >> 5;
    const int qr   = lane >> 2;
    const int qc   = lane & 3;

    const int qt = (int)gridDim.x - 1 - (int)blockIdx.x;
    const int h  = blockIdx.y;
    const int b  = blockIdx.z;
    const int q0 = qt * FQ;
    const size_t head_half = ((size_t)b * NH + h) * T * DH;
    const uint32_t* qbase = (const uint32_t*)(gq + head_half);
    const __half*   kbase = gk + head_half;
    const __half*   vbase = gv + head_half;

    const int ntiles = 2 * qt + 2;
    const float scale = 0.08838834764831845f * 1.4426950408889634f;

    const int lm_row  = lane & 15;
    const int lm_koff = (lane & 16) >> 2;
    const int k_row   = ((lane & 16) >> 1) + (lane & 7);
    const int k_koff  = (lane & 8) >> 1;
    const int v_kvoff = lane & 8;
    const int v_dcol  = (lane & 16) >> 2;

    // ---- Q fragments (registers) ----
    const int r0g = q0 + w * 16 + qr;
    uint32_t qf[8][4];
    {
        const uint32_t* q0p = qbase + (size_t)r0g * (DH / 2);
        const uint32_t* q1p = qbase + (size_t)(r0g + 8) * (DH / 2);
#pragma unroll
        for (int ks = 0; ks < 8; ks++) {
            qf[ks][0] = q0p[ks * 8 + qc];
            qf[ks][1] = q1p[ks * 8 + qc];
            qf[ks][2] = q0p[ks * 8 + qc + 4];
            qf[ks][3] = q1p[ks * 8 + qc + 4];
        }
    }

    float oa[16][4];
#pragma unroll
    for (int nf = 0; nf < 16; nf++)
#pragma unroll
        for (int r = 0; r < 4; r++) oa[nf][r] = 0.0f;
    float m0 = -1e30f, m1 = -1e30f, l0 = 0.0f, l1 = 0.0f;

    auto load_kv = [&](int kt) {
        const int s = kt % NBUF;
        const int kv0 = kt * FKV;
        const uint32_t kdst = sb + (uint32_t)(s * STG_U32) * 4;
        const uint32_t vdst = sb + (uint32_t)(s * STG_U32 + K_U32) * 4;
#pragma unroll
        for (int i = 0; i < 4; i++) {
            const int g = tid + i * 256;
            const int row = g >> 4, c = g & 15;
            cp16(kdst + (uint32_t)(row * KS2 + c * 4) * 4,
                 kbase + (size_t)(kv0 + row) * DH + c * 8);
            cp16(vdst + (uint32_t)(row * VS2 + c * 4) * 4,
                 vbase + (size_t)(kv0 + row) * DH + c * 8);
        }
        CP_COMMIT();
    };

    const uint32_t pw_addr = sb + (uint32_t)(P_OFF_U32 + w * 16 * PS2) * 4;
    uint32_t* Pw = smu + P_OFF_U32 + (w * 16) * PS2;

    float sf[8][4];
    auto compute_S = [&](int kt) {
#pragma unroll
        for (int nf = 0; nf < 8; nf++)
#pragma unroll
            for (int r = 0; r < 4; r++) sf[nf][r] = 0.0f;
        const uint32_t k_stage = sb + (uint32_t)((kt % NBUF) * STG_U32) * 4;
#pragma unroll
        for (int ks = 0; ks < 8; ks++) {
#pragma unroll
            for (int nfp = 0; nfp < 4; nfp++) {
                uint32_t kb0, kb1, kb2, kb3;
                ldsm4(kb0, kb1, kb2, kb3,
                      k_stage + (uint32_t)((nfp * 16 + k_row) * KS2
                                           + ks * 8 + k_koff) * 4);
                mma_f16_16n8k16(sf[2*nfp][0], sf[2*nfp][1],
                                sf[2*nfp][2], sf[2*nfp][3],
                                qf[ks][0], qf[ks][1], qf[ks][2], qf[ks][3],
                                kb0, kb1);
                mma_f16_16n8k16(sf[2*nfp+1][0], sf[2*nfp+1][1],
                                sf[2*nfp+1][2], sf[2*nfp+1][3],
                                qf[ks][0], qf[ks][1], qf[ks][2], qf[ks][3],
                                kb2, kb3);
            }
        }
    };

    // Prologue: stage first two KV tiles, compute S(0).
    load_kv(0);
    load_kv(1);
    cp_wait<1>();          // KV(0) complete (KV(1) may be in flight)
    __syncthreads();
    compute_S(0);

    for (int kt = 0; kt < ntiles; kt++) {
        // ---- softmax on S(kt): scale + causal mask + online update ----
        const int kv0 = kt * FKV;
        const bool dm = (kt >= ntiles - 2);
        float rm0 = -1e30f, rm1 = -1e30f;
#pragma unroll
        for (int nf = 0; nf < 8; nf++) {
            float v0 = sf[nf][0] * scale, v1 = sf[nf][1] * scale;
            float v2 = sf[nf][2] * scale, v3 = sf[nf][3] * scale;
            if (dm) {
                const int cg = kv0 + nf * 8 + 2 * qc;
                if (cg     > r0g)     v0 = -1e30f;
                if (cg + 1 > r0g)     v1 = -1e30f;
                if (cg     > r0g + 8) v2 = -1e30f;
                if (cg + 1 > r0g + 8) v3 = -1e30f;
            }
            sf[nf][0] = v0; sf[nf][1] = v1; sf[nf][2] = v2; sf[nf][3] = v3;
            rm0 = fmaxf(rm0, fmaxf(v0, v1));
            rm1 = fmaxf(rm1, fmaxf(v2, v3));
        }
        rm0 = fmaxf(rm0, __shfl_xor_sync(0xffffffffu, rm0, 1));
        rm0 = fmaxf(rm0, __shfl_xor_sync(0xffffffffu, rm0, 2));
        rm1 = fmaxf(rm1, __shfl_xor_sync(0xffffffffu, rm1, 1));
        rm1 = fmaxf(rm1, __shfl_xor_sync(0xffffffffu, rm1, 2));

        const float mn0 = fmaxf(m0, rm0), mn1 = fmaxf(m1, rm1);
        const float sc0 = fast_exp2(m0 - mn0), sc1 = fast_exp2(m1 - mn1);
        m0 = mn0; m1 = mn1;

        float rs0 = 0.0f, rs1 = 0.0f;
#pragma unroll
        for (int nf = 0; nf < 8; nf++) {
            const float p0 = fast_exp2(sf[nf][0] - mn0);
            const float p1 = fast_exp2(sf[nf][1] - mn0);
            const float p2 = fast_exp2(sf[nf][2] - mn1);
            const float p3 = fast_exp2(sf[nf][3] - mn1);
            rs0 += p0 + p1; rs1 += p2 + p3;
            Pw[qr       * PS2 + nf * 4 + qc] = pack2(p0, p1);
            Pw[(qr + 8) * PS2 + nf * 4 + qc] = pack2(p2, p3);
        }
        rs0 += __shfl_xor_sync(0xffffffffu, rs0, 1);
        rs0 += __shfl_xor_sync(0xffffffffu, rs0, 2);
        rs1 += __shfl_xor_sync(0xffffffffu, rs1, 1);
        rs1 += __shfl_xor_sync(0xffffffffu, rs1, 2);
        l0 = l0 * sc0 + rs0;
        l1 = l1 * sc1 + rs1;

#pragma unroll
        for (int nf = 0; nf < 16; nf++) {
            oa[nf][0] *= sc0; oa[nf][1] *= sc0;
            oa[nf][2] *= sc1; oa[nf][3] *= sc1;
        }
        __syncwarp();

        // ---- pipeline turn: ensure KV(kt+1) arrived, recycle buffer ----
        if (kt + 1 < ntiles) {
            cp_wait<0>();          // KV(kt+1) complete
            __syncthreads();       // all warps past PV(kt-1): buf (kt+2)%3 free
            if (kt + 2 < ntiles) load_kv(kt + 2);
            // S(kt+1) first (independent of P stores); sf recycled.
            compute_S(kt + 1);
        }

        // ---- PV(kt): O += P V ----
        const uint32_t v_stage =
            sb + (uint32_t)((kt % NBUF) * STG_U32 + K_U32) * 4;
#pragma unroll
        for (int ks = 0; ks < 4; ks++) {
            uint32_t pa0, pa1, pa2, pa3;
            ldsm4(pa0, pa1, pa2, pa3,
                  pw_addr + (uint32_t)(lm_row * PS2 + ks * 8 + lm_koff) * 4);
#pragma unroll
            for (int nfp = 0; nfp < 8; nfp++) {
                uint32_t v0, v1, v2, v3;
                ldsm4t(v0, v1, v2, v3,
                       v_stage + (uint32_t)((ks * 16 + v_kvoff + (lane & 7)) * VS2
                                            + nfp * 8 + v_dcol) * 4);
                mma_f16_16n8k16(oa[2*nfp][0], oa[2*nfp][1],
                                oa[2*nfp][2], oa[2*nfp][3],
                                pa0, pa1, pa2, pa3, v0, v1);
                mma_f16_16n8k16(oa[2*nfp+1][0], oa[2*nfp+1][1],
                                oa[2*nfp+1][2], oa[2*nfp+1][3],
                                pa0, pa1, pa2, pa3, v2, v3);
            }
        }
    }

    // ---- epilogue: normalize, pack fp16, store ----
    const float inv0 = 1.0f / l0, inv1 = 1.0f / l1;
    uint32_t* ob = (uint32_t*)(gout + head_half);
#pragma unroll
    for (int nf = 0; nf < 16; nf++) {
        ob[(size_t)r0g       * (DH / 2) + nf * 4 + qc] =
            pack2(oa[nf][0] * inv0, oa[nf][1] * inv0);
        ob[(size_t)(r0g + 8) * (DH / 2) + nf * 4 + qc] =
            pack2(oa[nf][2] * inv1, oa[nf][3] * inv1);
    }
}

// ---------------------------------------------------------------------------
extern "C" void kernel_launch(void* const* d_in, const int* in_sizes, int n_in,
                              void* d_out, int out_size)
{
    const float* src = (const float*)d_in[0];
    const float* Wq  = (const float*)d_in[1];
    const float* bq  = (const float*)d_in[2];
    const float* Wk  = (const float*)d_in[3];
    const float* bk  = (const float*)d_in[4];
    const float* Wv  = (const float*)d_in[5];
    const float* bv  = (const float*)d_in[6];
    const float* Wo  = (const float*)d_in[7];
    const float* bo  = (const float*)d_in[8];
    float* out = (float*)d_out;

    __half *q, *k, *v, *o, *a;
    uint32_t *w0, *w1, *w2, *w3;
    cudaGetSymbolAddress((void**)&q,  g_q);
    cudaGetSymbolAddress((void**)&k,  g_k);
    cudaGetSymbolAddress((void**)&v,  g_v);
    cudaGetSymbolAddress((void**)&o,  g_o);
    cudaGetSymbolAddress((void**)&a,  g_a);
    cudaGetSymbolAddress((void**)&w0, g_w0);
    cudaGetSymbolAddress((void**)&w1, g_w1);
    cudaGetSymbolAddress((void**)&w2, g_w2);
    cudaGetSymbolAddress((void**)&w3, g_w3);

    cudaFuncSetAttribute(flash4_kernel,
                         cudaFuncAttributeMaxDynamicSharedMemorySize,
                         FLASH_SMEM);
    cudaFuncSetAttribute(qkv_gemm_kernel,
                         cudaFuncAttributeMaxDynamicSharedMemorySize, GEMM_SMEM);
    cudaFuncSetAttribute(o_gemm_kernel,
                         cudaFuncAttributeMaxDynamicSharedMemorySize, GEMM_SMEM);

    // 1. Convert src -> fp16 and pack all 4 weights (one launch).
    ConvArgs ca;
    ca.w[0] = Wq; ca.w[1] = Wk; ca.w[2] = Wv; ca.w[3] = Wo;
    ca.wp[0] = w0; ca.wp[1] = w1; ca.wp[2] = w2; ca.wp[3] = w3;
    ca.src = (const float4*)src;
    ca.a_out = (uint2*)a;
    ca.src_n = MROWS * KDIM / 4;
    convert_kernel<<<dim3(1024, 5), 256>>>(ca);

    // 2. Fused Q/K/V projections.
    qkv_gemm_kernel<<<dim3(NDIM / 128, MROWS / 128, 3), 256, GEMM_SMEM>>>(
        a, w0, w1, w2, bq, bk, bv, q, k, v);

    // 3. fp16 flash attention (software-pipelined S/PV).
    flash4_kernel<<<dim3(T / FQ, NH, BSZ), 256, FLASH_SMEM>>>(q, k, v, o);

    // 4. O projection.
    o_gemm_kernel<<<dim3(NDIM / 128, MROWS / 128), 256, GEMM_SMEM>>>(
        o, w3, bo, out);
}

// round 15
// speedup vs baseline: 1.0354x; 1.0354x over previous
#include <cuda_runtime.h>
#include <cuda_fp16.h>
#include <math.h>
#include <stdint.h>

// Problem constants
#define BSZ 2
#define T   2048
#define C   2048
#define NH  16
#define DH  128
#define MROWS (BSZ * T)      // 4096
#define KDIM  C              // 2048
#define NDIM  C              // 2048

// Scratch (fp16 activations/weights; fp32 only at the final output)
__device__ __half  g_a[MROWS * KDIM];            // fp16 src
__device__ uint32_t g_w0[(KDIM / 2) * NDIM];     // Wq packed half2 (k-interleaved)
__device__ uint32_t g_w1[(KDIM / 2) * NDIM];
__device__ uint32_t g_w2[(KDIM / 2) * NDIM];
__device__ uint32_t g_w3[(KDIM / 2) * NDIM];
__device__ __half  g_q[BSZ * NH * T * DH];       // heads layout [b,h,t,d]
__device__ __half  g_k[BSZ * NH * T * DH];
__device__ __half  g_v[BSZ * NH * T * DH];
__device__ __half  g_o[BSZ * NH * T * DH];

// ---------------------------------------------------------------------------
// PTX helpers
// ---------------------------------------------------------------------------
__device__ __forceinline__ uint32_t smem_u32(const void* p) {
    uint32_t a;
    asm("{ .reg .u64 t; cvta.to.shared.u64 t, %1; cvt.u32.u64 %0, t; }"
        : "=r"(a) : "l"(p));
    return a;
}

__device__ __forceinline__ float fast_exp2(float x) {
    float y;
    asm("ex2.approx.f32 %0, %1;" : "=f"(y) : "f"(x));
    return y;
}

__device__ __forceinline__ uint32_t pack2(float lo, float hi) {
    __half2 h = __floats2half2_rn(lo, hi);
    return *(uint32_t*)&h;
}

__device__ __forceinline__ void cp16(uint32_t dst, const void* src) {
    asm volatile("cp.async.cg.shared.global [%0], [%1], 16;"
                 :: "r"(dst), "l"(src));
}
#define CP_COMMIT() asm volatile("cp.async.commit_group;" ::: "memory")
template <int N>
__device__ __forceinline__ void cp_wait() {
    asm volatile("cp.async.wait_group %0;" :: "n"(N) : "memory");
}

__device__ __forceinline__ void ldsm4(uint32_t& r0, uint32_t& r1,
                                      uint32_t& r2, uint32_t& r3, uint32_t a) {
    asm volatile("ldmatrix.sync.aligned.m8n8.x4.shared.b16 {%0,%1,%2,%3}, [%4];"
                 : "=r"(r0), "=r"(r1), "=r"(r2), "=r"(r3) : "r"(a));
}
__device__ __forceinline__ void ldsm4t(uint32_t& r0, uint32_t& r1,
                                       uint32_t& r2, uint32_t& r3, uint32_t a) {
    asm volatile("ldmatrix.sync.aligned.m8n8.x4.trans.shared.b16 {%0,%1,%2,%3}, [%4];"
                 : "=r"(r0), "=r"(r1), "=r"(r2), "=r"(r3) : "r"(a));
}

__device__ __forceinline__ void mma_f16_16n8k16(
    float& d0, float& d1, float& d2, float& d3,
    uint32_t a0, uint32_t a1, uint32_t a2, uint32_t a3,
    uint32_t b0, uint32_t b1)
{
    asm volatile(
        "mma.sync.aligned.m16n8k16.row.col.f32.f16.f16.f32 "
        "{%0,%1,%2,%3}, {%4,%5,%6,%7}, {%8,%9}, {%0,%1,%2,%3};\n"
        : "+f"(d0), "+f"(d1), "+f"(d2), "+f"(d3)
        : "r"(a0), "r"(a1), "r"(a2), "r"(a3), "r"(b0), "r"(b1));
}

// ---------------------------------------------------------------------------
// Pre-pass: y==0 converts src fp32->fp16; y==1..4 pack weights into
// k-interleaved half2: wp[k2*N + n] = half2(W[2k2][n], W[2k2+1][n]).
// ---------------------------------------------------------------------------
struct ConvArgs {
    const float* w[4];
    uint32_t*    wp[4];
    const float4* src;
    uint2*        a_out;
    int           src_n;
};

__global__ void convert_kernel(ConvArgs ca) {
    const int y = blockIdx.y;
    if (y == 0) {
        int i = blockIdx.x * blockDim.x + threadIdx.x;
        const int stride = gridDim.x * blockDim.x;
        for (; i < ca.src_n; i += stride) {
            float4 v = ca.src[i];
            uint2 o;
            o.x = pack2(v.x, v.y);
            o.y = pack2(v.z, v.w);
            ca.a_out[i] = o;
        }
    } else {
        const float* W  = ca.w[y - 1];
        uint32_t*    wp = ca.wp[y - 1];
        const int total = (KDIM / 2) * (NDIM / 4);
        int i = blockIdx.x * blockDim.x + threadIdx.x;
        const int stride = gridDim.x * blockDim.x;
        for (; i < total; i += stride) {
            const int k2 = i >> 9;
            const int nc = (i & 511) * 4;
            const float4 r0 = *(const float4*)&W[(size_t)(2 * k2)     * NDIM + nc];
            const float4 r1 = *(const float4*)&W[(size_t)(2 * k2 + 1) * NDIM + nc];
            uint4 o;
            o.x = pack2(r0.x, r1.x);
            o.y = pack2(r0.y, r1.y);
            o.z = pack2(r0.z, r1.z);
            o.w = pack2(r0.w, r1.w);
            *(uint4*)&wp[(size_t)k2 * NDIM + nc] = o;
        }
    }
}

// ---------------------------------------------------------------------------
// fp16 HMMA GEMM (R11 configuration): out = A @ W + bias
// Block tile 128x128, K-slab 64 (4 m16n8k16 steps), 3-stage cp.async,
// 256 threads, 8 warps (2x4), warp tile 64x32. A-frags via ldmatrix.x4;
// B-frags (scalar LDS) double-buffered across k16-steps.
// ---------------------------------------------------------------------------
#define BK 64
#define NKS (KDIM / BK)          // 32
#define STAGES 3
#define AS2 36
#define BS2 136
#define A_ST_U32 (128 * AS2)     // 4608
#define B_ST_U32 (32 * BS2)      // 4352
#define ST_U32 (A_ST_U32 + B_ST_U32)   // 8960
#define GEMM_SMEM (STAGES * ST_U32 * 4)  // 107520 bytes

template <bool GATHER_A, bool OUT_F32>
__device__ void gemm_body(
    const __half* __restrict__ A, const uint32_t* __restrict__ Wp,
    const float* __restrict__ bias, void* __restrict__ out_v,
    int m_base, int n_base)
{
    extern __shared__ uint32_t smu[];
    const uint32_t sb = smem_u32(smu);
    const int tid  = threadIdx.x;
    const int lane = tid & 31;
    const int w    = tid >> 5;
    const int wm   = (w >> 2) * 64;
    const int wn   = (w & 3) * 32;

    const int lm_row  = lane & 15;
    const int lm_koff = (lane & 16) >> 2;

    uint32_t a_off[4], b_off[4];
    const __half* a_fix[4];
    const uint32_t* b_fix[4];
#pragma unroll
    for (int i = 0; i < 4; i++) {
        const int g  = tid + i * 256;
        const int ar = g >> 3;
        const int ac = g & 7;
        a_off[i] = (uint32_t)(ar * AS2 + ac * 4) * 4;
        if (GATHER_A) {
            const int m = m_base + ar;
            a_fix[i] = A + (size_t)(m >> 11) * (NH * T * DH)
                         + (size_t)(m & 2047) * DH + ac * 8;
        } else {
            a_fix[i] = A + (size_t)(m_base + ar) * KDIM + ac * 8;
        }
        const int br = g >> 5;
        const int bc = g & 31;
        b_off[i] = (uint32_t)(A_ST_U32 + br * BS2 + bc * 4) * 4;
        b_fix[i] = Wp + (size_t)br * NDIM + n_base + bc * 4;
    }

    auto load_slab = [&](int ks) {
        const int s = ks % STAGES;
        const uint32_t stage = sb + (uint32_t)(s * ST_U32) * 4;
        const int k0 = ks * BK;
#pragma unroll
        for (int i = 0; i < 4; i++) {
            const __half* asrc;
            if (GATHER_A)
                asrc = a_fix[i] + (size_t)(k0 >> 7) * (T * DH) + (k0 & 127);
            else
                asrc = a_fix[i] + k0;
            cp16(stage + a_off[i], asrc);
            cp16(stage + b_off[i], b_fix[i] + (size_t)(k0 / 2) * NDIM);
        }
        CP_COMMIT();
    };

    float acc[4][4][4];
#pragma unroll
    for (int mf = 0; mf < 4; mf++)
#pragma unroll
        for (int nf = 0; nf < 4; nf++)
#pragma unroll
            for (int r = 0; r < 4; r++) acc[mf][nf][r] = 0.0f;

    load_slab(0);
    load_slab(1);

    const int qr = lane >> 2;
    const int qc = lane & 3;

    for (int ks = 0; ks < NKS; ks++) {
        if (ks >= NKS - 1) cp_wait<0>(); else cp_wait<1>();
        __syncthreads();
        // Barrier proves all warps finished slab ks-1, whose buffer
        // (== buffer of ks+2 in the 3-stage ring) we now overwrite.
        if (ks + 2 < NKS) load_slab(ks + 2);

        const uint32_t st_off = (uint32_t)((ks % STAGES) * ST_U32);
        const uint32_t* Bs = smu + st_off + A_ST_U32;
        const uint32_t a_stage = sb + st_off * 4;

        uint32_t bfr[2][4][2];
#pragma unroll
        for (int nf = 0; nf < 4; nf++) {
            const int cn = wn + nf * 8 + qr;
            bfr[0][nf][0] = Bs[qc       * BS2 + cn];
            bfr[0][nf][1] = Bs[(qc + 4) * BS2 + cn];
        }

#pragma unroll
        for (int s2 = 0; s2 < 4; s2++) {
            const int cur = s2 & 1;
            if (s2 < 3) {
                const int pb = (s2 + 1) * 8;
#pragma unroll
                for (int nf = 0; nf < 4; nf++) {
                    const int cn = wn + nf * 8 + qr;
                    bfr[cur ^ 1][nf][0] = Bs[(pb + qc)     * BS2 + cn];
                    bfr[cur ^ 1][nf][1] = Bs[(pb + qc + 4) * BS2 + cn];
                }
            }
            const int pb = s2 * 8;
#pragma unroll
            for (int mf = 0; mf < 4; mf++) {
                uint32_t a0, a1, a2, a3;
                ldsm4(a0, a1, a2, a3,
                      a_stage + (uint32_t)((wm + mf * 16 + lm_row) * AS2
                                           + pb + lm_koff) * 4);
#pragma unroll
                for (int nf = 0; nf < 4; nf++)
                    mma_f16_16n8k16(acc[mf][nf][0], acc[mf][nf][1],
                                    acc[mf][nf][2], acc[mf][nf][3],
                                    a0, a1, a2, a3,
                                    bfr[cur][nf][0], bfr[cur][nf][1]);
            }
        }
    }

    // ---- epilogue ----
#pragma unroll
    for (int mf = 0; mf < 4; mf++) {
        const int row0 = m_base + wm + mf * 16 + qr;
#pragma unroll
        for (int nf = 0; nf < 4; nf++) {
            const int col = n_base + wn + nf * 8 + 2 * qc;
            const float bx = bias[col];
            const float by = bias[col + 1];
#pragma unroll
            for (int half_i = 0; half_i < 2; half_i++) {
                const int row = row0 + half_i * 8;
                const float vx = acc[mf][nf][half_i * 2 + 0] + bx;
                const float vy = acc[mf][nf][half_i * 2 + 1] + by;
                if (OUT_F32) {
                    float2 v; v.x = vx; v.y = vy;
                    *(float2*)&((float*)out_v)[(size_t)row * NDIM + col] = v;
                } else {
                    const int b = row >> 11, t = row & 2047;
                    const int h = col >> 7,  d = col & 127;
                    __half* ho = (__half*)out_v;
                    const size_t idx = (((size_t)b * NH + h) * T + t) * DH + d;
                    *(uint32_t*)&ho[idx] = pack2(vx, vy);
                }
            }
        }
    }
}

__global__ __launch_bounds__(256, 2) void qkv_gemm_kernel(
    const __half* __restrict__ A,
    const uint32_t* __restrict__ w0, const uint32_t* __restrict__ w1,
    const uint32_t* __restrict__ w2,
    const float* __restrict__ b0, const float* __restrict__ b1,
    const float* __restrict__ b2,
    __half* __restrict__ o0, __half* __restrict__ o1, __half* __restrict__ o2)
{
    const int z = blockIdx.z;
    const uint32_t* W  = (z == 0) ? w0 : (z == 1) ? w1 : w2;
    const float* bias  = (z == 0) ? b0 : (z == 1) ? b1 : b2;
    __half*      out   = (z == 0) ? o0 : (z == 1) ? o1 : o2;
    gemm_body<false, false>(A, W, bias, out,
                            blockIdx.y * 128, blockIdx.x * 128);
}

__global__ __launch_bounds__(256, 2) void o_gemm_kernel(
    const __half* __restrict__ A, const uint32_t* __restrict__ W,
    const float* __restrict__ bias, float* __restrict__ out)
{
    gemm_body<true, true>(A, W, bias, out,
                          blockIdx.y * 128, blockIdx.x * 128);
}

// ---------------------------------------------------------------------------
// fp16 flash attention (causal). BQ=128, BKV=64, D=128, 256 threads,
// 8 warps x 16 q-rows. P kept in REGISTERS: the fp32 C-fragment of S packs
// directly into the fp16 A-fragment for the PV mma (no smem round-trip).
// K via ldmatrix.x4, V via ldmatrix.x4.trans. Double-buffered cp.async KV.
// smem (u32): K[2][64][68], V[2][64][68]  = 69632 bytes
// ---------------------------------------------------------------------------
#define FQ 128
#define FKV 64
#define KS2 68
#define VS2 68
#define K_U32 (FKV * KS2)                // 4352
#define V_U32 (FKV * VS2)                // 4352
#define STG_U32 (K_U32 + V_U32)          // 8704
#define FLASH_SMEM (2 * STG_U32 * 4)     // 69632 bytes

__global__ __launch_bounds__(256) void flash5_kernel(
    const __half* __restrict__ gq, const __half* __restrict__ gk,
    const __half* __restrict__ gv, __half* __restrict__ gout)
{
    extern __shared__ uint32_t smu[];
    const uint32_t sb = smem_u32(smu);
    const int tid  = threadIdx.x;
    const int lane = tid & 31;
    const int w    = tid >> 5;
    const int qr   = lane >> 2;
    const int qc   = lane & 3;

    const int qt = (int)gridDim.x - 1 - (int)blockIdx.x;
    const int h  = blockIdx.y;
    const int b  = blockIdx.z;
    const int q0 = qt * FQ;
    const size_t head_half = ((size_t)b * NH + h) * T * DH;
    const uint32_t* qbase = (const uint32_t*)(gq + head_half);
    const __half*   kbase = gk + head_half;
    const __half*   vbase = gv + head_half;

    const int ntiles = 2 * qt + 2;
    const float scale = 0.08838834764831845f * 1.4426950408889634f;

    const int k_row   = ((lane & 16) >> 1) + (lane & 7);
    const int k_koff  = (lane & 8) >> 1;
    const int v_kvoff = lane & 8;
    const int v_dcol  = (lane & 16) >> 2;

    // ---- Q fragments (registers) ----
    const int r0g = q0 + w * 16 + qr;
    uint32_t qf[8][4];
    {
        const uint32_t* q0p = qbase + (size_t)r0g * (DH / 2);
        const uint32_t* q1p = qbase + (size_t)(r0g + 8) * (DH / 2);
#pragma unroll
        for (int ks = 0; ks < 8; ks++) {
            qf[ks][0] = q0p[ks * 8 + qc];
            qf[ks][1] = q1p[ks * 8 + qc];
            qf[ks][2] = q0p[ks * 8 + qc + 4];
            qf[ks][3] = q1p[ks * 8 + qc + 4];
        }
    }

    float oa[16][4];
#pragma unroll
    for (int nf = 0; nf < 16; nf++)
#pragma unroll
        for (int r = 0; r < 4; r++) oa[nf][r] = 0.0f;
    float m0 = -1e30f, m1 = -1e30f, l0 = 0.0f, l1 = 0.0f;

    auto load_kv = [&](int kt) {
        const int s = kt & 1;
        const int kv0 = kt * FKV;
        const uint32_t kdst = sb + (uint32_t)(s * STG_U32) * 4;
        const uint32_t vdst = sb + (uint32_t)(s * STG_U32 + K_U32) * 4;
#pragma unroll
        for (int i = 0; i < 4; i++) {
            const int g = tid + i * 256;
            const int row = g >> 4, c = g & 15;
            cp16(kdst + (uint32_t)(row * KS2 + c * 4) * 4,
                 kbase + (size_t)(kv0 + row) * DH + c * 8);
            cp16(vdst + (uint32_t)(row * VS2 + c * 4) * 4,
                 vbase + (size_t)(kv0 + row) * DH + c * 8);
        }
        CP_COMMIT();
    };

    load_kv(0);

    for (int kt = 0; kt < ntiles; kt++) {
        const int s = kt & 1;
        cp_wait<0>();
        __syncthreads();
        // Barrier proves all warps done with buffer (kt+1)&1; prefetch safe.
        if (kt + 1 < ntiles) load_kv(kt + 1);

        const uint32_t k_stage = sb + (uint32_t)(s * STG_U32) * 4;
        const uint32_t v_stage = sb + (uint32_t)(s * STG_U32 + K_U32) * 4;

        // ---- S = Q K^T ----
        float sf[8][4];
#pragma unroll
        for (int nf = 0; nf < 8; nf++)
#pragma unroll
            for (int r = 0; r < 4; r++) sf[nf][r] = 0.0f;

#pragma unroll
        for (int ks = 0; ks < 8; ks++) {
#pragma unroll
            for (int nfp = 0; nfp < 4; nfp++) {
                uint32_t kb0, kb1, kb2, kb3;
                ldsm4(kb0, kb1, kb2, kb3,
                      k_stage + (uint32_t)((nfp * 16 + k_row) * KS2
                                           + ks * 8 + k_koff) * 4);
                mma_f16_16n8k16(sf[2*nfp][0], sf[2*nfp][1],
                                sf[2*nfp][2], sf[2*nfp][3],
                                qf[ks][0], qf[ks][1], qf[ks][2], qf[ks][3],
                                kb0, kb1);
                mma_f16_16n8k16(sf[2*nfp+1][0], sf[2*nfp+1][1],
                                sf[2*nfp+1][2], sf[2*nfp+1][3],
                                qf[ks][0], qf[ks][1], qf[ks][2], qf[ks][3],
                                kb2, kb3);
            }
        }

        // ---- scale (base-2) + causal mask + row max ----
        const int kv0 = kt * FKV;
        const bool dm = (kt >= ntiles - 2);
        float rm0 = -1e30f, rm1 = -1e30f;
#pragma unroll
        for (int nf = 0; nf < 8; nf++) {
            float v0 = sf[nf][0] * scale, v1 = sf[nf][1] * scale;
            float v2 = sf[nf][2] * scale, v3 = sf[nf][3] * scale;
            if (dm) {
                const int cg = kv0 + nf * 8 + 2 * qc;
                if (cg     > r0g)     v0 = -1e30f;
                if (cg + 1 > r0g)     v1 = -1e30f;
                if (cg     > r0g + 8) v2 = -1e30f;
                if (cg + 1 > r0g + 8) v3 = -1e30f;
            }
            sf[nf][0] = v0; sf[nf][1] = v1; sf[nf][2] = v2; sf[nf][3] = v3;
            rm0 = fmaxf(rm0, fmaxf(v0, v1));
            rm1 = fmaxf(rm1, fmaxf(v2, v3));
        }
        rm0 = fmaxf(rm0, __shfl_xor_sync(0xffffffffu, rm0, 1));
        rm0 = fmaxf(rm0, __shfl_xor_sync(0xffffffffu, rm0, 2));
        rm1 = fmaxf(rm1, __shfl_xor_sync(0xffffffffu, rm1, 1));
        rm1 = fmaxf(rm1, __shfl_xor_sync(0xffffffffu, rm1, 2));

        const float mn0 = fmaxf(m0, rm0), mn1 = fmaxf(m1, rm1);
        const float sc0 = fast_exp2(m0 - mn0), sc1 = fast_exp2(m1 - mn1);
        m0 = mn0; m1 = mn1;

        // ---- P = exp2(S - m): pack DIRECTLY into PV A-fragments ----
        // C-frag (c0,c1 @ row qr; c2,c3 @ row qr+8) == A-frag layout:
        //   pfr[ks] = { pack(2ks:c0,c1), pack(2ks:c2,c3),
        //               pack(2ks+1:c0,c1), pack(2ks+1:c2,c3) }
        uint32_t pfr[4][4];
        float rs0 = 0.0f, rs1 = 0.0f;
#pragma unroll
        for (int nf = 0; nf < 8; nf++) {
            const float p0 = fast_exp2(sf[nf][0] - mn0);
            const float p1 = fast_exp2(sf[nf][1] - mn0);
            const float p2 = fast_exp2(sf[nf][2] - mn1);
            const float p3 = fast_exp2(sf[nf][3] - mn1);
            rs0 += p0 + p1; rs1 += p2 + p3;
            pfr[nf >> 1][(nf & 1) * 2 + 0] = pack2(p0, p1);
            pfr[nf >> 1][(nf & 1) * 2 + 1] = pack2(p2, p3);
        }
        rs0 += __shfl_xor_sync(0xffffffffu, rs0, 1);
        rs0 += __shfl_xor_sync(0xffffffffu, rs0, 2);
        rs1 += __shfl_xor_sync(0xffffffffu, rs1, 1);
        rs1 += __shfl_xor_sync(0xffffffffu, rs1, 2);
        l0 = l0 * sc0 + rs0;
        l1 = l1 * sc1 + rs1;

        // ---- rescale O ----
#pragma unroll
        for (int nf = 0; nf < 16; nf++) {
            oa[nf][0] *= sc0; oa[nf][1] *= sc0;
            oa[nf][2] *= sc1; oa[nf][3] *= sc1;
        }

        // ---- O += P V (P straight from registers) ----
#pragma unroll
        for (int ks = 0; ks < 4; ks++) {
#pragma unroll
            for (int nfp = 0; nfp < 8; nfp++) {
                uint32_t v0, v1, v2, v3;
                ldsm4t(v0, v1, v2, v3,
                       v_stage + (uint32_t)((ks * 16 + v_kvoff + (lane & 7)) * VS2
                                            + nfp * 8 + v_dcol) * 4);
                mma_f16_16n8k16(oa[2*nfp][0], oa[2*nfp][1],
                                oa[2*nfp][2], oa[2*nfp][3],
                                pfr[ks][0], pfr[ks][1], pfr[ks][2], pfr[ks][3],
                                v0, v1);
                mma_f16_16n8k16(oa[2*nfp+1][0], oa[2*nfp+1][1],
                                oa[2*nfp+1][2], oa[2*nfp+1][3],
                                pfr[ks][0], pfr[ks][1], pfr[ks][2], pfr[ks][3],
                                v2, v3);
            }
        }
    }

    // ---- epilogue: normalize, pack fp16, store ----
    const float inv0 = 1.0f / l0, inv1 = 1.0f / l1;
    uint32_t* ob = (uint32_t*)(gout + head_half);
#pragma unroll
    for (int nf = 0; nf < 16; nf++) {
        ob[(size_t)r0g       * (DH / 2) + nf * 4 + qc] =
            pack2(oa[nf][0] * inv0, oa[nf][1] * inv0);
        ob[(size_t)(r0g + 8) * (DH / 2) + nf * 4 + qc] =
            pack2(oa[nf][2] * inv1, oa[nf][3] * inv1);
    }
}

// ---------------------------------------------------------------------------
extern "C" void kernel_launch(void* const* d_in, const int* in_sizes, int n_in,
                              void* d_out, int out_size)
{
    const float* src = (const float*)d_in[0];
    const float* Wq  = (const float*)d_in[1];
    const float* bq  = (const float*)d_in[2];
    const float* Wk  = (const float*)d_in[3];
    const float* bk  = (const float*)d_in[4];
    const float* Wv  = (const float*)d_in[5];
    const float* bv  = (const float*)d_in[6];
    const float* Wo  = (const float*)d_in[7];
    const float* bo  = (const float*)d_in[8];
    float* out = (float*)d_out;

    __half *q, *k, *v, *o, *a;
    uint32_t *w0, *w1, *w2, *w3;
    cudaGetSymbolAddress((void**)&q,  g_q);
    cudaGetSymbolAddress((void**)&k,  g_k);
    cudaGetSymbolAddress((void**)&v,  g_v);
    cudaGetSymbolAddress((void**)&o,  g_o);
    cudaGetSymbolAddress((void**)&a,  g_a);
    cudaGetSymbolAddress((void**)&w0, g_w0);
    cudaGetSymbolAddress((void**)&w1, g_w1);
    cudaGetSymbolAddress((void**)&w2, g_w2);
    cudaGetSymbolAddress((void**)&w3, g_w3);

    cudaFuncSetAttribute(flash5_kernel,
                         cudaFuncAttributeMaxDynamicSharedMemorySize,
                         FLASH_SMEM);
    cudaFuncSetAttribute(qkv_gemm_kernel,
                         cudaFuncAttributeMaxDynamicSharedMemorySize, GEMM_SMEM);
    cudaFuncSetAttribute(o_gemm_kernel,
                         cudaFuncAttributeMaxDynamicSharedMemorySize, GEMM_SMEM);

    // 1. Convert src -> fp16 and pack all 4 weights (one launch).
    ConvArgs ca;
    ca.w[0] = Wq; ca.w[1] = Wk; ca.w[2] = Wv; ca.w[3] = Wo;
    ca.wp[0] = w0; ca.wp[1] = w1; ca.wp[2] = w2; ca.wp[3] = w3;
    ca.src = (const float4*)src;
    ca.a_out = (uint2*)a;
    ca.src_n = MROWS * KDIM / 4;
    convert_kernel<<<dim3(1024, 5), 256>>>(ca);

    // 2. Fused Q/K/V projections.
    qkv_gemm_kernel<<<dim3(NDIM / 128, MROWS / 128, 3), 256, GEMM_SMEM>>>(
        a, w0, w1, w2, bq, bk, bv, q, k, v);

    // 3. fp16 flash attention (P in registers).
    flash5_kernel<<<dim3(T / FQ, NH, BSZ), 256, FLASH_SMEM>>>(q, k, v, o);

    // 4. O projection.
    o_gemm_kernel<<<dim3(NDIM / 128, MROWS / 128), 256, GEMM_SMEM>>>(
        o, w3, bo, out);
}